// round 6
// baseline (speedup 1.0000x reference)
#include <cuda_runtime.h>

// Problem constants: B=4, C=256, H=W=64, K=7, GROUPS=16, GC=16, CR=64
#define HW   4096
#define WDIM 64

typedef unsigned long long ull;

// Scratch for conv1 output x: [4][64][4096] fp32 = 4 MB
__device__ float g_xbuf[4 * 64 * 4096];

__device__ __forceinline__ ull pack2(float lo, float hi) {
    ull r;
    asm("mov.b64 %0, {%1, %2};" : "=l"(r) : "f"(lo), "f"(hi));
    return r;
}
__device__ __forceinline__ void unpack2(ull v, float &lo, float &hi) {
    asm("mov.b64 {%0, %1}, %2;" : "=f"(lo), "=f"(hi) : "l"(v));
}
__device__ __forceinline__ void fma2(ull &d, ull a, ull b) {
    asm("fma.rn.f32x2 %0, %1, %2, %0;" : "+l"(d) : "l"(a), "l"(b));
}
__device__ __forceinline__ unsigned smem_u32(const void* p) {
    return (unsigned)__cvta_generic_to_shared(p);
}
__device__ __forceinline__ void cp_async16(unsigned dst, const void* src) {
    asm volatile("cp.async.cg.shared.global [%0], [%1], 16;" :: "r"(dst), "l"(src));
}
__device__ __forceinline__ void cp_async4(unsigned dst, const void* src) {
    asm volatile("cp.async.ca.shared.global [%0], [%1], 4;" :: "r"(dst), "l"(src));
}
__device__ __forceinline__ void cp_async4z(unsigned dst, const void* src, int sz) {
    asm volatile("cp.async.ca.shared.global [%0], [%1], 4, %2;"
                 :: "r"(dst), "l"(src), "r"(sz));
}
__device__ __forceinline__ void cp_commit() {
    asm volatile("cp.async.commit_group;");
}

// ---------------------------------------------------------------------------
// Kernel 1: conv1 (1x1, 256->64) + BN + ReLU -> g_xbuf
// Double-buffered cp.async staging over the four 64-r blocks.
// ---------------------------------------------------------------------------
#define C1BUF 4352   // 64*68 floats per staging buffer

__device__ __forceinline__ void conv1_prefetch(float* w1t, float* gsh,
        const float* __restrict__ w1, const float* __restrict__ guide,
        int b, int gpix0, int r0, int tid)
{
    #pragma unroll
    for (int i = tid; i < 4096; i += 256) {
        int m = i >> 6, rr = i & 63;
        cp_async4(smem_u32(w1t + rr * 68 + m), w1 + m * 256 + r0 + rr);
    }
    #pragma unroll
    for (int i = tid; i < 1024; i += 256) {
        int rr = i >> 4, px4 = (i & 15) * 4;
        cp_async16(smem_u32(gsh + rr * 68 + px4),
                   guide + (size_t)(b * 256 + r0 + rr) * HW + gpix0 + px4);
    }
}

__global__ __launch_bounds__(256, 2)
void conv1_kernel(const float* __restrict__ guide,
                  const float* __restrict__ w1,
                  const float* __restrict__ gamma,
                  const float* __restrict__ beta,
                  const float* __restrict__ mean,
                  const float* __restrict__ var)
{
    extern __shared__ float csm[];          // 4 * 4352 floats = 69632 B
    float* w1tb[2] = { csm,              csm + C1BUF };
    float* gshb[2] = { csm + 2 * C1BUF,  csm + 3 * C1BUF };

    const int tid   = threadIdx.x;
    const int b     = blockIdx.y;
    const int gpix0 = blockIdx.x * 64;
    const int mq = tid >> 4, pq = tid & 15;
    const int m0 = mq * 4,   p0 = pq * 4;

    ull acc[4][2];
    #pragma unroll
    for (int i = 0; i < 4; i++) { acc[i][0] = 0ull; acc[i][1] = 0ull; }

    conv1_prefetch(w1tb[0], gshb[0], w1, guide, b, gpix0, 0, tid);   cp_commit();
    conv1_prefetch(w1tb[1], gshb[1], w1, guide, b, gpix0, 64, tid);  cp_commit();

    for (int blk = 0; blk < 4; blk++) {
        if (blk < 3) asm volatile("cp.async.wait_group 1;");
        else         asm volatile("cp.async.wait_group 0;");
        __syncthreads();

        const float* w1t = w1tb[blk & 1];
        const float* gsh = gshb[blk & 1];

        #pragma unroll 8
        for (int rr = 0; rr < 64; rr++) {
            float4 w4 = *(const float4*)&w1t[rr * 68 + m0];
            ulonglong2 xv = *(const ulonglong2*)&gsh[rr * 68 + p0];
            ull wp;
            wp = pack2(w4.x, w4.x); fma2(acc[0][0], xv.x, wp); fma2(acc[0][1], xv.y, wp);
            wp = pack2(w4.y, w4.y); fma2(acc[1][0], xv.x, wp); fma2(acc[1][1], xv.y, wp);
            wp = pack2(w4.z, w4.z); fma2(acc[2][0], xv.x, wp); fma2(acc[2][1], xv.y, wp);
            wp = pack2(w4.w, w4.w); fma2(acc[3][0], xv.x, wp); fma2(acc[3][1], xv.y, wp);
        }
        __syncthreads();

        if (blk + 2 < 4) {
            conv1_prefetch(w1tb[blk & 1], gshb[blk & 1], w1, guide, b, gpix0,
                           (blk + 2) * 64, tid);
            cp_commit();
        }
    }

    #pragma unroll
    for (int i = 0; i < 4; i++) {
        int m = m0 + i;
        float inv = gamma[m] * rsqrtf(var[m] + 1e-5f);
        float bsh = beta[m] - mean[m] * inv;
        float v0, v1, v2, v3;
        unpack2(acc[i][0], v0, v1);
        unpack2(acc[i][1], v2, v3);
        v0 = fmaxf(fmaf(v0, inv, bsh), 0.f);
        v1 = fmaxf(fmaf(v1, inv, bsh), 0.f);
        v2 = fmaxf(fmaf(v2, inv, bsh), 0.f);
        v3 = fmaxf(fmaf(v3, inv, bsh), 0.f);
        *(float4*)&g_xbuf[(b * 64 + m) * HW + gpix0 + p0] = make_float4(v0, v1, v2, v3);
    }
}

// ---------------------------------------------------------------------------
// Kernel 2: fused conv2 + 7x7 aggregation + residual.
// Tile = 16x8 px, 1 group, 1 batch per CTA. 256 threads, 100.6 KB smem,
// 2 CTA/SM. Phase 1: 4 warps, 2 kq per warp, 8 px (two 4-px chunks) per
// thread -> fma-bound. Phase 2: packed f32x2 aggregation.
// ---------------------------------------------------------------------------
#define TPX 128                 // pixels per tile (16 rows x 8 cols)
#define FRS 16                  // f_sh row stride (floats), rows are 14 wide
#define FCH 356                 // f_sh channel stride (89 16B-chunks, odd)
#define NK2 56                  // padded k count (8 kq * 7)

__global__ __launch_bounds__(256, 2)
void fused_kernel(const float* __restrict__ feat,
                  const float* __restrict__ w2,
                  const float* __restrict__ b2,
                  float* __restrict__ out)
{
    extern __shared__ float smem[];
    float* x_sh   = smem;                      // [64][128]      32768 B
    float* f_sh   = x_sh + 64 * TPX;           // 16*356 f       22784 B
    float* w2_sh  = f_sh + 16 * FCH;           // [64][64]       16384 B
    float* wgt_sh = w2_sh + 64 * 64;           // [56][128]      28672 B -> 100608 B

    const int tid  = threadIdx.x;
    const int g    = blockIdx.x;
    const int tile = blockIdx.y;
    const int b    = blockIdx.z;
    const int y0 = (tile >> 3) * 16;
    const int x0 = (tile & 7) * 8;
    const int w    = tid >> 5;
    const int lane = tid & 31;

    // ---- stage x tile [64 r][128 px] via cp.async 16B  (group 0)
    {
        const float* src0 = g_xbuf + (size_t)(b * 64) * HW + y0 * WDIM + x0;
        #pragma unroll
        for (int i = tid; i < 2048; i += 256) {
            int r  = i >> 5;
            int c4 = (i & 31) * 4;
            int row = c4 >> 3, col = c4 & 7;
            cp_async16(smem_u32(x_sh + r * TPX + c4),
                       src0 + (size_t)r * HW + row * WDIM + col);
        }
    }
    cp_commit();

    // ---- stage feature tile + 3-px halo via cp.async 4B + zfill  (group 1)
    {
        const float* fch0 = feat + (size_t)(b * 256 + g * 16) * HW;
        for (int i = tid; i < 16 * 308; i += 256) {
            int c   = i / 308;
            int rem = i - c * 308;
            int yy  = rem / 14;
            int xx  = rem - yy * 14;
            int gy = y0 + yy - 3, gx = x0 + xx - 3;
            bool ok = ((unsigned)gy < 64u) && ((unsigned)gx < 64u);
            const float* src = fch0 + (size_t)c * HW + (ok ? gy * WDIM + gx : 0);
            cp_async4z(smem_u32(f_sh + c * FCH + yy * FRS + xx), src, ok ? 4 : 0);
        }
    }
    cp_commit();

    // ---- zero the pad slots of w2_sh (kk==7 columns, and kq==7 rows)
    for (int i = tid; i < 64 * 16; i += 256) {
        int r = i >> 4, s = i & 15;
        int slot = (s < 8) ? (s * 8 + 7) : (56 + (s - 8));
        w2_sh[r * 64 + slot] = 0.f;
    }
    // ---- stage w2 (plain floats, layout [r][kq*8 + kk]) — coalesced over r
    for (int i = tid; i < 49 * 64; i += 256) {
        int k = i >> 6, r = i & 63;
        int kqi = k / 7, kki = k - kqi * 7;
        w2_sh[r * 64 + kqi * 8 + kki] = w2[(g * 49 + k) * 64 + r];
    }

    asm volatile("cp.async.wait_group 1;");   // x done; f may still be in flight
    __syncthreads();

    // -------- Phase 1: wgt[56][128] = w2_g @ x + b2
    // 4 warps; kq = 2w + half-warp (0..7); 8 px/thread as chunks po and po+64.
    if (w < 4) {
        const int kq = 2 * w + (lane >> 4);
        const int po = (lane & 15) * 4;

        ull acc[7][4];
        #pragma unroll
        for (int kk = 0; kk < 7; kk++) {
            int k = kq * 7 + kk;
            float bv = (k < 49) ? b2[g * 49 + k] : 0.f;
            ull bp = pack2(bv, bv);
            acc[kk][0] = bp; acc[kk][1] = bp; acc[kk][2] = bp; acc[kk][3] = bp;
        }
        const float* xp = x_sh + po;
        const float* wp = w2_sh + kq * 8;
        #pragma unroll 4
        for (int r = 0; r < 64; r++) {
            ulonglong2 xA = *(const ulonglong2*)(xp + r * TPX);        // px po..po+3
            ulonglong2 xB = *(const ulonglong2*)(xp + r * TPX + 64);   // px po+64..
            float4 wa = *(const float4*)(wp + r * 64);                 // half-warp bcast
            float4 wb = *(const float4*)(wp + r * 64 + 4);
            ull t;
            t = pack2(wa.x, wa.x); fma2(acc[0][0], xA.x, t); fma2(acc[0][1], xA.y, t);
                                   fma2(acc[0][2], xB.x, t); fma2(acc[0][3], xB.y, t);
            t = pack2(wa.y, wa.y); fma2(acc[1][0], xA.x, t); fma2(acc[1][1], xA.y, t);
                                   fma2(acc[1][2], xB.x, t); fma2(acc[1][3], xB.y, t);
            t = pack2(wa.z, wa.z); fma2(acc[2][0], xA.x, t); fma2(acc[2][1], xA.y, t);
                                   fma2(acc[2][2], xB.x, t); fma2(acc[2][3], xB.y, t);
            t = pack2(wa.w, wa.w); fma2(acc[3][0], xA.x, t); fma2(acc[3][1], xA.y, t);
                                   fma2(acc[3][2], xB.x, t); fma2(acc[3][3], xB.y, t);
            t = pack2(wb.x, wb.x); fma2(acc[4][0], xA.x, t); fma2(acc[4][1], xA.y, t);
                                   fma2(acc[4][2], xB.x, t); fma2(acc[4][3], xB.y, t);
            t = pack2(wb.y, wb.y); fma2(acc[5][0], xA.x, t); fma2(acc[5][1], xA.y, t);
                                   fma2(acc[5][2], xB.x, t); fma2(acc[5][3], xB.y, t);
            t = pack2(wb.z, wb.z); fma2(acc[6][0], xA.x, t); fma2(acc[6][1], xA.y, t);
                                   fma2(acc[6][2], xB.x, t); fma2(acc[6][3], xB.y, t);
        }
        #pragma unroll
        for (int kk = 0; kk < 7; kk++) {
            int k = kq * 7 + kk;
            *(ulonglong2*)&wgt_sh[k * TPX + po] =
                make_ulonglong2(acc[kk][0], acc[kk][1]);
            *(ulonglong2*)&wgt_sh[k * TPX + po + 64] =
                make_ulonglong2(acc[kk][2], acc[kk][3]);
        }
    }

    asm volatile("cp.async.wait_group 0;");   // f tile complete (hidden under GEMM)
    __syncthreads();

    // -------- Phase 2: 7x7 dynamic aggregation (packed f32x2) + residual
    // warp covers 2 pixel rows; lane = (rowhalf, channel); 8 px x 1 ch per thread
    {
        const int rowA = 2 * w + (lane >> 4);
        const int c    = lane & 15;

        const float* fbase = f_sh + c * FCH;
        const float* wbase = wgt_sh + rowA * 8;

        ull accp[4] = {0ull, 0ull, 0ull, 0ull};

        #pragma unroll 1
        for (int di = 0; di < 7; di++) {
            const float* frow = fbase + (rowA + di) * FRS;
            float4 A = *(const float4*)(frow);
            float4 B = *(const float4*)(frow + 4);
            float4 C = *(const float4*)(frow + 8);
            float4 D = *(const float4*)(frow + 12);
            ull fra[7];
            fra[0] = pack2(A.x, A.y); fra[1] = pack2(A.z, A.w);
            fra[2] = pack2(B.x, B.y); fra[3] = pack2(B.z, B.w);
            fra[4] = pack2(C.x, C.y); fra[5] = pack2(C.z, C.w);
            fra[6] = pack2(D.x, D.y);
            ull frb[6];
            frb[0] = pack2(A.y, A.z); frb[1] = pack2(A.w, B.x);
            frb[2] = pack2(B.y, B.z); frb[3] = pack2(B.w, C.x);
            frb[4] = pack2(C.y, C.z); frb[5] = pack2(C.w, D.x);

            #pragma unroll
            for (int dj = 0; dj < 7; dj += 2) {
                int k = di * 7 + dj;
                ulonglong2 wv01 = *(const ulonglong2*)(wbase + k * TPX);
                ulonglong2 wv23 = *(const ulonglong2*)(wbase + k * TPX + 4);
                int s = dj >> 1;
                fma2(accp[0], wv01.x, fra[s]);
                fma2(accp[1], wv01.y, fra[s + 1]);
                fma2(accp[2], wv23.x, fra[s + 2]);
                fma2(accp[3], wv23.y, fra[s + 3]);
            }
            #pragma unroll
            for (int dj = 1; dj < 7; dj += 2) {
                int k = di * 7 + dj;
                ulonglong2 wv01 = *(const ulonglong2*)(wbase + k * TPX);
                ulonglong2 wv23 = *(const ulonglong2*)(wbase + k * TPX + 4);
                int s = (dj - 1) >> 1;
                fma2(accp[0], wv01.x, frb[s]);
                fma2(accp[1], wv01.y, frb[s + 1]);
                fma2(accp[2], wv23.x, frb[s + 2]);
                fma2(accp[3], wv23.y, frb[s + 3]);
            }
        }

        float acc[8];
        unpack2(accp[0], acc[0], acc[1]);
        unpack2(accp[1], acc[2], acc[3]);
        unpack2(accp[2], acc[4], acc[5]);
        unpack2(accp[3], acc[6], acc[7]);
        #pragma unroll
        for (int j = 0; j < 8; j++)
            acc[j] += fbase[(rowA + 3) * FRS + j + 3];

        float* op = &out[(size_t)(b * 256 + g * 16 + c) * HW + (y0 + rowA) * WDIM + x0];
        *(float4*)(op)     = make_float4(acc[0], acc[1], acc[2], acc[3]);
        *(float4*)(op + 4) = make_float4(acc[4], acc[5], acc[6], acc[7]);
    }
}

// ---------------------------------------------------------------------------
extern "C" void kernel_launch(void* const* d_in, const int* in_sizes, int n_in,
                              void* d_out, int out_size)
{
    const float* feat  = (const float*)d_in[0];
    const float* guide = (const float*)d_in[1];
    const float* w1    = (const float*)d_in[2];
    const float* gamma = (const float*)d_in[3];
    const float* beta  = (const float*)d_in[4];
    const float* mean  = (const float*)d_in[5];
    const float* var   = (const float*)d_in[6];
    const float* w2    = (const float*)d_in[7];
    const float* b2    = (const float*)d_in[8];
    float* out = (float*)d_out;

    const int c1_smem = 4 * C1BUF * 4;   // 69632
    cudaFuncSetAttribute(conv1_kernel,
                         cudaFuncAttributeMaxDynamicSharedMemorySize, c1_smem);
    conv1_kernel<<<dim3(64, 4), 256, c1_smem>>>(guide, w1, gamma, beta, mean, var);

    const int smem_bytes = (64 * TPX + 16 * FCH + 64 * 64 + NK2 * TPX) * 4; // 100608
    cudaFuncSetAttribute(fused_kernel,
                         cudaFuncAttributeMaxDynamicSharedMemorySize, smem_bytes);
    fused_kernel<<<dim3(16, 32, 4), 256, smem_bytes>>>(feat, w2, b2, out);
}

// round 7
// speedup vs baseline: 1.0594x; 1.0594x over previous
#include <cuda_runtime.h>

// Problem constants: B=4, C=256, H=W=64, K=7, GROUPS=16, GC=16, CR=64
#define HW   4096
#define WDIM 64

typedef unsigned long long ull;

// Scratch: conv1 output x [4][64][4096] (4 MB) + dynamic weights [4][784][4096] (51.4 MB)
__device__ float g_xbuf[4 * 64 * 4096];
__device__ float g_wgt[4 * 784 * 4096];

__device__ __forceinline__ ull pack2(float lo, float hi) {
    ull r;
    asm("mov.b64 %0, {%1, %2};" : "=l"(r) : "f"(lo), "f"(hi));
    return r;
}
__device__ __forceinline__ void unpack2(ull v, float &lo, float &hi) {
    asm("mov.b64 {%0, %1}, %2;" : "=f"(lo), "=f"(hi) : "l"(v));
}
__device__ __forceinline__ void fma2(ull &d, ull a, ull b) {
    asm("fma.rn.f32x2 %0, %1, %2, %0;" : "+l"(d) : "l"(a), "l"(b));
}
__device__ __forceinline__ unsigned smem_u32(const void* p) {
    return (unsigned)__cvta_generic_to_shared(p);
}
__device__ __forceinline__ void cp_async16(unsigned dst, const void* src) {
    asm volatile("cp.async.cg.shared.global [%0], [%1], 16;" :: "r"(dst), "l"(src));
}
__device__ __forceinline__ void cp_async16z(unsigned dst, const void* src, int sz) {
    asm volatile("cp.async.cg.shared.global [%0], [%1], 16, %2;"
                 :: "r"(dst), "l"(src), "r"(sz));
}
__device__ __forceinline__ void cp_async4(unsigned dst, const void* src) {
    asm volatile("cp.async.ca.shared.global [%0], [%1], 4;" :: "r"(dst), "l"(src));
}
__device__ __forceinline__ void cp_async4z(unsigned dst, const void* src, int sz) {
    asm volatile("cp.async.ca.shared.global [%0], [%1], 4, %2;"
                 :: "r"(dst), "l"(src), "r"(sz));
}
__device__ __forceinline__ void cp_commit() {
    asm volatile("cp.async.commit_group;");
}

// ---------------------------------------------------------------------------
// Kernel 1: conv1 (1x1, 256->64) + BN + ReLU -> g_xbuf
// 32-px tiles, 128 threads, grid 512, 4 CTA/SM, double-buffered cp.async.
// ---------------------------------------------------------------------------
#define C1W 4352   // 64*68 floats (w1t buffer)
#define C1G 2304   // 64*36 floats (guide buffer)

__device__ __forceinline__ void conv1_prefetch(float* w1t, float* gsh,
        const float* __restrict__ w1, const float* __restrict__ guide,
        int b, int gpix0, int r0, int tid)
{
    #pragma unroll
    for (int i = tid; i < 4096; i += 128) {
        int m = i >> 6, rr = i & 63;
        cp_async4(smem_u32(w1t + rr * 68 + m), w1 + m * 256 + r0 + rr);
    }
    #pragma unroll
    for (int i = tid; i < 512; i += 128) {
        int rr = i >> 3, px4 = (i & 7) * 4;
        cp_async16(smem_u32(gsh + rr * 36 + px4),
                   guide + (size_t)(b * 256 + r0 + rr) * HW + gpix0 + px4);
    }
}

__global__ __launch_bounds__(128, 4)
void conv1_kernel(const float* __restrict__ guide,
                  const float* __restrict__ w1,
                  const float* __restrict__ gamma,
                  const float* __restrict__ beta,
                  const float* __restrict__ mean,
                  const float* __restrict__ var)
{
    extern __shared__ float csm[];          // 2*C1W + 2*C1G floats = 53248 B
    float* w1tb[2] = { csm,            csm + C1W };
    float* gshb[2] = { csm + 2 * C1W,  csm + 2 * C1W + C1G };

    const int tid   = threadIdx.x;
    const int b     = blockIdx.y;
    const int gpix0 = blockIdx.x * 32;
    const int mq = tid >> 3, pq = tid & 7;
    const int m0 = mq * 4,   p0 = pq * 4;

    ull acc[4][2];
    #pragma unroll
    for (int i = 0; i < 4; i++) { acc[i][0] = 0ull; acc[i][1] = 0ull; }

    conv1_prefetch(w1tb[0], gshb[0], w1, guide, b, gpix0, 0, tid);   cp_commit();
    conv1_prefetch(w1tb[1], gshb[1], w1, guide, b, gpix0, 64, tid);  cp_commit();

    for (int blk = 0; blk < 4; blk++) {
        if (blk < 3) asm volatile("cp.async.wait_group 1;");
        else         asm volatile("cp.async.wait_group 0;");
        __syncthreads();

        const float* w1t = w1tb[blk & 1];
        const float* gsh = gshb[blk & 1];

        #pragma unroll 8
        for (int rr = 0; rr < 64; rr++) {
            float4 w4 = *(const float4*)&w1t[rr * 68 + m0];
            ulonglong2 xv = *(const ulonglong2*)&gsh[rr * 36 + p0];
            ull wp;
            wp = pack2(w4.x, w4.x); fma2(acc[0][0], xv.x, wp); fma2(acc[0][1], xv.y, wp);
            wp = pack2(w4.y, w4.y); fma2(acc[1][0], xv.x, wp); fma2(acc[1][1], xv.y, wp);
            wp = pack2(w4.z, w4.z); fma2(acc[2][0], xv.x, wp); fma2(acc[2][1], xv.y, wp);
            wp = pack2(w4.w, w4.w); fma2(acc[3][0], xv.x, wp); fma2(acc[3][1], xv.y, wp);
        }
        __syncthreads();

        if (blk + 2 < 4) {
            conv1_prefetch(w1tb[blk & 1], gshb[blk & 1], w1, guide, b, gpix0,
                           (blk + 2) * 64, tid);
            cp_commit();
        }
    }

    #pragma unroll
    for (int i = 0; i < 4; i++) {
        int m = m0 + i;
        float inv = gamma[m] * rsqrtf(var[m] + 1e-5f);
        float bsh = beta[m] - mean[m] * inv;
        float v0, v1, v2, v3;
        unpack2(acc[i][0], v0, v1);
        unpack2(acc[i][1], v2, v3);
        v0 = fmaxf(fmaf(v0, inv, bsh), 0.f);
        v1 = fmaxf(fmaf(v1, inv, bsh), 0.f);
        v2 = fmaxf(fmaf(v2, inv, bsh), 0.f);
        v3 = fmaxf(fmaf(v3, inv, bsh), 0.f);
        *(float4*)&g_xbuf[(b * 64 + m) * HW + gpix0 + p0] = make_float4(v0, v1, v2, v3);
    }
}

// ---------------------------------------------------------------------------
// Kernel 2a: dynamic-weight GEMM  g_wgt[b][k][p] = w2[k] @ x[:,p] + b2[k]
// CTA = [112 k] x [128 px], 512 threads, 64 KB smem, 2 CTA/SM (32 warps).
// warp = 7 k's, lane = 4 px. Grid (7 kb, 32 pt, 4 b) = 896 CTAs.
// ---------------------------------------------------------------------------
__global__ __launch_bounds__(512, 2)
void gemm2_kernel(const float* __restrict__ w2,
                  const float* __restrict__ b2)
{
    extern __shared__ float smem[];
    float* x_sh  = smem;              // [64][128]  32768 B
    float* w2t   = smem + 64 * 128;   // [64][128]  32768 B  ([r][wq*8+i], i<7 used)

    const int tid  = threadIdx.x;
    const int kb   = blockIdx.x;          // k-block (112 k's)
    const int pt   = blockIdx.y;          // pixel block (128 px)
    const int b    = blockIdx.z;
    const int wq   = tid >> 5;            // warp 0..15
    const int lane = tid & 31;

    // stage x tile (cp.async 16B, fully coalesced)
    {
        const float* src = g_xbuf + (size_t)(b * 64) * HW + pt * 128;
        #pragma unroll
        for (int i = tid; i < 2048; i += 512) {
            int r = i >> 5, ch = i & 31;
            cp_async16(smem_u32(x_sh + r * 128 + ch * 4), src + (size_t)r * HW + ch * 4);
        }
    }
    // stage w2 transposed: w2t[r][wq*8+i] = w2[kb*112 + wq*7 + i][r]  (pad i=7)
    {
        #pragma unroll
        for (int idx = tid; idx < 64 * 128; idx += 512) {
            int r = idx >> 7, s = idx & 127;
            int wqi = s >> 3, ii = s & 7;
            const float* src = w2 + (size_t)(kb * 112 + wqi * 7 + (ii < 7 ? ii : 0)) * 64 + r;
            cp_async4z(smem_u32(w2t + idx), src, ii < 7 ? 4 : 0);
        }
    }
    cp_commit();

    const int k0 = kb * 112 + wq * 7;
    ull acc[7][2];
    #pragma unroll
    for (int i = 0; i < 7; i++) {
        float bv = b2[k0 + i];
        ull bp = pack2(bv, bv);
        acc[i][0] = bp; acc[i][1] = bp;
    }

    asm volatile("cp.async.wait_group 0;");
    __syncthreads();

    const float* xp = x_sh + lane * 4;
    const float* wp = w2t + wq * 8;
    #pragma unroll 4
    for (int r = 0; r < 64; r++) {
        ulonglong2 xv = *(const ulonglong2*)(xp + r * 128);
        float4 wa = *(const float4*)(wp + r * 128);       // half... warp-uniform bcast
        float4 wb = *(const float4*)(wp + r * 128 + 4);
        ull t;
        t = pack2(wa.x, wa.x); fma2(acc[0][0], xv.x, t); fma2(acc[0][1], xv.y, t);
        t = pack2(wa.y, wa.y); fma2(acc[1][0], xv.x, t); fma2(acc[1][1], xv.y, t);
        t = pack2(wa.z, wa.z); fma2(acc[2][0], xv.x, t); fma2(acc[2][1], xv.y, t);
        t = pack2(wa.w, wa.w); fma2(acc[3][0], xv.x, t); fma2(acc[3][1], xv.y, t);
        t = pack2(wb.x, wb.x); fma2(acc[4][0], xv.x, t); fma2(acc[4][1], xv.y, t);
        t = pack2(wb.y, wb.y); fma2(acc[5][0], xv.x, t); fma2(acc[5][1], xv.y, t);
        t = pack2(wb.z, wb.z); fma2(acc[6][0], xv.x, t); fma2(acc[6][1], xv.y, t);
    }

    float* dst = g_wgt + ((size_t)b * 784 + k0) * HW + pt * 128 + lane * 4;
    #pragma unroll
    for (int i = 0; i < 7; i++)
        *(ulonglong2*)(dst + (size_t)i * HW) = make_ulonglong2(acc[i][0], acc[i][1]);
}

// ---------------------------------------------------------------------------
// Kernel 2b: 7x7 dynamic aggregation + residual.
// Tile = 16x8 px, 1 group, 1 batch per CTA. 256 threads, 47.9 KB smem,
// 4 CTA/SM. f staged with aligned 16B chunks (phys window gx = x0-4..x0+11,
// all-or-nothing zfill); taps use phys = j + dj + 1 -> fra/frb pairing.
// ---------------------------------------------------------------------------
#define FRS 16                  // f_sh row stride (16 phys cols)
#define FCH 356                 // f_sh channel stride (22*16 + 4, odd chunks)

__global__ __launch_bounds__(256, 4)
void agg_kernel(const float* __restrict__ feat,
                float* __restrict__ out)
{
    extern __shared__ float smem[];
    float* f_sh   = smem;               // 16*356 f   22784 B
    float* wgt_sh = smem + 16 * FCH;    // [49][128]  25088 B  -> 47872 B

    const int tid  = threadIdx.x;
    const int g    = blockIdx.x;
    const int tile = blockIdx.y;
    const int b    = blockIdx.z;
    const int y0 = (tile >> 3) * 16;
    const int x0 = (tile & 7) * 8;
    const int w    = tid >> 5;
    const int lane = tid & 31;

    // ---- stage wgt tile [49][16 rows x 8 px] via cp.async 16B
    {
        const float* src0 = g_wgt + ((size_t)b * 784 + g * 49) * HW + y0 * WDIM + x0;
        for (int i = tid; i < 1568; i += 256) {
            int k = i >> 5, rem = i & 31;
            int row = rem >> 1, half = rem & 1;
            cp_async16(smem_u32(wgt_sh + k * 128 + row * 8 + half * 4),
                       src0 + (size_t)k * HW + row * WDIM + half * 4);
        }
    }
    // ---- stage feature: 16 ch x 22 rows x 4 aligned 16B chunks, zfill OOB
    {
        const float* fch0 = feat + (size_t)(b * 256 + g * 16) * HW;
        for (int i = tid; i < 1408; i += 256) {
            int c   = i / 88;
            int rem = i - c * 88;
            int yy  = rem >> 2;
            int q   = rem & 3;
            int gy  = y0 + yy - 3;
            int gx0 = x0 - 4 + q * 4;
            bool ok = ((unsigned)gy < 64u) && ((unsigned)gx0 <= 60u);
            const float* src = fch0 + (size_t)c * HW + (ok ? gy * WDIM + gx0 : 0);
            cp_async16z(smem_u32(f_sh + c * FCH + yy * FRS + q * 4), src, ok ? 16 : 0);
        }
    }
    cp_commit();
    asm volatile("cp.async.wait_group 0;");
    __syncthreads();

    // ---- aggregation: warp covers 2 rows; lane = (rowhalf, channel); 8 px/thread
    {
        const int rowA = 2 * w + (lane >> 4);
        const int c    = lane & 15;

        const float* fbase = f_sh + c * FCH;
        const float* wbase = wgt_sh + rowA * 8;

        ull accp[4] = {0ull, 0ull, 0ull, 0ull};

        #pragma unroll 1
        for (int di = 0; di < 7; di++) {
            const float* frow = fbase + (rowA + di) * FRS;
            float4 A = *(const float4*)(frow);
            float4 B = *(const float4*)(frow + 4);
            float4 C = *(const float4*)(frow + 8);
            float4 D = *(const float4*)(frow + 12);
            // even-phys pairs (indices 1..6 used): fra[q] = (frow[2q], frow[2q+1])
            ull fra[7];
            fra[1] = pack2(A.z, A.w); fra[2] = pack2(B.x, B.y);
            fra[3] = pack2(B.z, B.w); fra[4] = pack2(C.x, C.y);
            fra[5] = pack2(C.z, C.w); fra[6] = pack2(D.x, D.y);
            // odd-phys pairs: frb[q] = (frow[2q+1], frow[2q+2])
            ull frb[7];
            frb[0] = pack2(A.y, A.z); frb[1] = pack2(A.w, B.x);
            frb[2] = pack2(B.y, B.z); frb[3] = pack2(B.w, C.x);
            frb[4] = pack2(C.y, C.z); frb[5] = pack2(C.w, D.x);
            frb[6] = pack2(D.y, D.z);

            // tap dj: pair for accp[t] starts at phys 2t + dj + 1
            #pragma unroll
            for (int dj = 0; dj < 7; dj += 2) {      // even dj -> frb[t + dj/2]
                int k = di * 7 + dj;
                ulonglong2 wv01 = *(const ulonglong2*)(wbase + k * 128);
                ulonglong2 wv23 = *(const ulonglong2*)(wbase + k * 128 + 4);
                int s = dj >> 1;
                fma2(accp[0], wv01.x, frb[s]);
                fma2(accp[1], wv01.y, frb[s + 1]);
                fma2(accp[2], wv23.x, frb[s + 2]);
                fma2(accp[3], wv23.y, frb[s + 3]);
            }
            #pragma unroll
            for (int dj = 1; dj < 7; dj += 2) {      // odd dj -> fra[t + (dj+1)/2]
                int k = di * 7 + dj;
                ulonglong2 wv01 = *(const ulonglong2*)(wbase + k * 128);
                ulonglong2 wv23 = *(const ulonglong2*)(wbase + k * 128 + 4);
                int s = (dj + 1) >> 1;
                fma2(accp[0], wv01.x, fra[s]);
                fma2(accp[1], wv01.y, fra[s + 1]);
                fma2(accp[2], wv23.x, fra[s + 2]);
                fma2(accp[3], wv23.y, fra[s + 3]);
            }
        }

        float acc[8];
        unpack2(accp[0], acc[0], acc[1]);
        unpack2(accp[1], acc[2], acc[3]);
        unpack2(accp[2], acc[4], acc[5]);
        unpack2(accp[3], acc[6], acc[7]);
        #pragma unroll
        for (int j = 0; j < 8; j++)                  // residual: phys = j + 4
            acc[j] += fbase[(rowA + 3) * FRS + j + 4];

        float* op = &out[(size_t)(b * 256 + g * 16 + c) * HW + (y0 + rowA) * WDIM + x0];
        *(float4*)(op)     = make_float4(acc[0], acc[1], acc[2], acc[3]);
        *(float4*)(op + 4) = make_float4(acc[4], acc[5], acc[6], acc[7]);
    }
}

// ---------------------------------------------------------------------------
extern "C" void kernel_launch(void* const* d_in, const int* in_sizes, int n_in,
                              void* d_out, int out_size)
{
    const float* feat  = (const float*)d_in[0];
    const float* guide = (const float*)d_in[1];
    const float* w1    = (const float*)d_in[2];
    const float* gamma = (const float*)d_in[3];
    const float* beta  = (const float*)d_in[4];
    const float* mean  = (const float*)d_in[5];
    const float* var   = (const float*)d_in[6];
    const float* w2    = (const float*)d_in[7];
    const float* b2    = (const float*)d_in[8];
    float* out = (float*)d_out;

    const int c1_smem = (2 * C1W + 2 * C1G) * 4;          // 53248
    cudaFuncSetAttribute(conv1_kernel,
                         cudaFuncAttributeMaxDynamicSharedMemorySize, c1_smem);
    conv1_kernel<<<dim3(128, 4), 128, c1_smem>>>(guide, w1, gamma, beta, mean, var);

    const int g_smem = (64 * 128 + 64 * 128) * 4;         // 65536
    cudaFuncSetAttribute(gemm2_kernel,
                         cudaFuncAttributeMaxDynamicSharedMemorySize, g_smem);
    gemm2_kernel<<<dim3(7, 32, 4), 512, g_smem>>>(w2, b2);

    const int a_smem = (16 * FCH + 49 * 128) * 4;         // 47872
    cudaFuncSetAttribute(agg_kernel,
                         cudaFuncAttributeMaxDynamicSharedMemorySize, a_smem);
    agg_kernel<<<dim3(16, 32, 4), 256, a_smem>>>(feat, out);
}

// round 9
// speedup vs baseline: 1.3251x; 1.2508x over previous
#include <cuda_runtime.h>

// Problem constants: B=4, C=256, H=W=64, K=7, GROUPS=16, GC=16, CR=64
#define HW   4096
#define WDIM 64

typedef unsigned long long ull;

// Scratch (static device globals — no allocs):
__device__ float g_xbuf[4 * 64 * 4096];        // conv1 output x           4 MB
__device__ float g_wgt[4 * 784 * 4096];        // dynamic weights          51.4 MB
__device__ float g_w1f[64 * 256];              // w1 transposed [r][m], BN-folded
__device__ float g_b1f[64];                    // folded conv1 bias
__device__ float g_w2p[64 * 896];              // w2 transposed+padded [r][kb*128+wq*8+ii]

__device__ __forceinline__ ull pack2(float lo, float hi) {
    ull r;
    asm("mov.b64 %0, {%1, %2};" : "=l"(r) : "f"(lo), "f"(hi));
    return r;
}
__device__ __forceinline__ void unpack2(ull v, float &lo, float &hi) {
    asm("mov.b64 {%0, %1}, %2;" : "=f"(lo), "=f"(hi) : "l"(v));
}
__device__ __forceinline__ void fma2(ull &d, ull a, ull b) {
    asm("fma.rn.f32x2 %0, %1, %2, %0;" : "+l"(d) : "l"(a), "l"(b));
}
__device__ __forceinline__ unsigned smem_u32(const void* p) {
    return (unsigned)__cvta_generic_to_shared(p);
}
__device__ __forceinline__ void cp_async16(unsigned dst, const void* src) {
    asm volatile("cp.async.cg.shared.global [%0], [%1], 16;" :: "r"(dst), "l"(src));
}
__device__ __forceinline__ void cp_async16z(unsigned dst, const void* src, int sz) {
    asm volatile("cp.async.cg.shared.global [%0], [%1], 16, %2;"
                 :: "r"(dst), "l"(src), "r"(sz));
}
__device__ __forceinline__ void cp_commit() {
    asm volatile("cp.async.commit_group;");
}

// ---------------------------------------------------------------------------
// Kernel 0: prep — fold BN into transposed w1; transpose+pad w2 into the
// exact smem layout gemm2 consumes. Grid 224 x 256 threads.
// ---------------------------------------------------------------------------
__global__ __launch_bounds__(256)
void prep_kernel(const float* __restrict__ w1,
                 const float* __restrict__ gamma,
                 const float* __restrict__ beta,
                 const float* __restrict__ mean,
                 const float* __restrict__ var,
                 const float* __restrict__ w2)
{
    int idx = blockIdx.x * 256 + threadIdx.x;

    if (idx < 64) {
        float inv = gamma[idx] * rsqrtf(var[idx] + 1e-5f);
        g_b1f[idx] = beta[idx] - mean[idx] * inv;
    }
    if (idx < 64 * 256) {                 // w1f[r][m] = w1[m][r] * inv[m]
        int r = idx >> 6, m = idx & 63;
        float inv = gamma[m] * rsqrtf(var[m] + 1e-5f);
        g_w1f[idx] = w1[m * 256 + r] * inv;
    }
    if (idx < 64 * 896) {                 // w2p[r][kb*128 + wq*8 + ii]
        int r = idx / 896, s = idx - r * 896;
        int kb = s >> 7, rem = s & 127;
        int wq = rem >> 3, ii = rem & 7;
        float v = 0.f;
        if (ii < 7) {
            int k = kb * 112 + wq * 7 + ii;     // always < 784
            v = w2[k * 64 + r];
        }
        g_w2p[idx] = v;
    }
}

// ---------------------------------------------------------------------------
// Kernel 1: conv1 (1x1, 256->64, BN folded) + ReLU -> g_xbuf
// 64-px tiles, 256 threads, grid (64,4)=256, 2 CTA/SM (98 KB smem).
// Full w1f staged once (coalesced 16B); guide double-buffered.
// ---------------------------------------------------------------------------
#define C1G 4352   // 64*68 floats per guide buffer

__global__ __launch_bounds__(256, 2)
void conv1_kernel(const float* __restrict__ guide)
{
    extern __shared__ float csm[];
    float* w1s = csm;                    // [256 r][64 m]   65536 B
    float* gb[2] = { csm + 16384, csm + 16384 + C1G };   // 2 x 17408 B

    const int tid   = threadIdx.x;
    const int b     = blockIdx.y;
    const int gpix0 = blockIdx.x * 64;
    const int mq = tid >> 4, pq = tid & 15;
    const int m0 = mq * 4,   p0 = pq * 4;

    // stage all of w1f (coalesced 16B) + guide block 0  -> group A
    #pragma unroll
    for (int i = tid; i < 4096; i += 256)
        cp_async16(smem_u32(w1s + i * 4), g_w1f + i * 4);
    #pragma unroll
    for (int i = tid; i < 1024; i += 256) {
        int rr = i >> 4, px4 = (i & 15) * 4;
        cp_async16(smem_u32(gb[0] + rr * 68 + px4),
                   guide + (size_t)(b * 256 + rr) * HW + gpix0 + px4);
    }
    cp_commit();
    // guide block 1 -> group B
    #pragma unroll
    for (int i = tid; i < 1024; i += 256) {
        int rr = i >> 4, px4 = (i & 15) * 4;
        cp_async16(smem_u32(gb[1] + rr * 68 + px4),
                   guide + (size_t)(b * 256 + 64 + rr) * HW + gpix0 + px4);
    }
    cp_commit();

    // bias-seeded accumulators
    ull acc[4][2];
    #pragma unroll
    for (int i = 0; i < 4; i++) {
        float bv = g_b1f[m0 + i];
        ull bp = pack2(bv, bv);
        acc[i][0] = bp; acc[i][1] = bp;
    }

    for (int blk = 0; blk < 4; blk++) {
        if (blk < 3) asm volatile("cp.async.wait_group 1;");
        else         asm volatile("cp.async.wait_group 0;");
        __syncthreads();

        const float* wb  = w1s + blk * 64 * 64;
        const float* gsh = gb[blk & 1];

        #pragma unroll 8
        for (int rr = 0; rr < 64; rr++) {
            float4 w4 = *(const float4*)&wb[rr * 64 + m0];
            ulonglong2 xv = *(const ulonglong2*)&gsh[rr * 68 + p0];
            ull wp;
            wp = pack2(w4.x, w4.x); fma2(acc[0][0], xv.x, wp); fma2(acc[0][1], xv.y, wp);
            wp = pack2(w4.y, w4.y); fma2(acc[1][0], xv.x, wp); fma2(acc[1][1], xv.y, wp);
            wp = pack2(w4.z, w4.z); fma2(acc[2][0], xv.x, wp); fma2(acc[2][1], xv.y, wp);
            wp = pack2(w4.w, w4.w); fma2(acc[3][0], xv.x, wp); fma2(acc[3][1], xv.y, wp);
        }
        __syncthreads();

        if (blk + 2 < 4) {
            float* dstb = gb[blk & 1];
            #pragma unroll
            for (int i = tid; i < 1024; i += 256) {
                int rr = i >> 4, px4 = (i & 15) * 4;
                cp_async16(smem_u32(dstb + rr * 68 + px4),
                           guide + (size_t)(b * 256 + (blk + 2) * 64 + rr) * HW + gpix0 + px4);
            }
            cp_commit();
        }
    }

    #pragma unroll
    for (int i = 0; i < 4; i++) {
        float v0, v1, v2, v3;
        unpack2(acc[i][0], v0, v1);
        unpack2(acc[i][1], v2, v3);
        v0 = fmaxf(v0, 0.f); v1 = fmaxf(v1, 0.f);
        v2 = fmaxf(v2, 0.f); v3 = fmaxf(v3, 0.f);
        *(float4*)&g_xbuf[(b * 64 + m0 + i) * HW + gpix0 + p0] = make_float4(v0, v1, v2, v3);
    }
}

// ---------------------------------------------------------------------------
// Kernel 2a: dynamic-weight GEMM  g_wgt[b][k][p] = w2[k] @ x[:,p] + b2[k]
// CTA = [112 k] x [128 px], 512 threads, 64 KB smem, 2 CTA/SM.
// w2 tile staged coalesced from the pre-padded g_w2p layout.
// ---------------------------------------------------------------------------
__global__ __launch_bounds__(512, 2)
void gemm2_kernel(const float* __restrict__ b2)
{
    extern __shared__ float smem[];
    float* x_sh = smem;              // [64][128]  32768 B
    float* w2t  = smem + 64 * 128;   // [64][128]  32768 B ([r][wq*8+ii])

    const int tid  = threadIdx.x;
    const int kb   = blockIdx.x;
    const int pt   = blockIdx.y;
    const int b    = blockIdx.z;
    const int wq   = tid >> 5;
    const int lane = tid & 31;

    // stage x tile (coalesced 16B)
    {
        const float* src = g_xbuf + (size_t)(b * 64) * HW + pt * 128;
        #pragma unroll
        for (int i = tid; i < 2048; i += 512) {
            int r = i >> 5, ch = i & 31;
            cp_async16(smem_u32(x_sh + r * 128 + ch * 4), src + (size_t)r * HW + ch * 4);
        }
    }
    // stage w2 tile from pre-padded layout (coalesced 16B)
    {
        const float* src = g_w2p + kb * 128;
        #pragma unroll
        for (int i = tid; i < 2048; i += 512) {
            int r = i >> 5, s4 = (i & 31) * 4;
            cp_async16(smem_u32(w2t + r * 128 + s4), src + r * 896 + s4);
        }
    }
    cp_commit();

    const int k0 = kb * 112 + wq * 7;
    ull acc[7][2];
    #pragma unroll
    for (int i = 0; i < 7; i++) {
        float bv = b2[k0 + i];
        ull bp = pack2(bv, bv);
        acc[i][0] = bp; acc[i][1] = bp;
    }

    asm volatile("cp.async.wait_group 0;");
    __syncthreads();

    const float* xp = x_sh + lane * 4;
    const float* wp = w2t + wq * 8;
    #pragma unroll 4
    for (int r = 0; r < 64; r++) {
        ulonglong2 xv = *(const ulonglong2*)(xp + r * 128);
        float4 wa = *(const float4*)(wp + r * 128);       // warp-uniform bcast
        float4 wb = *(const float4*)(wp + r * 128 + 4);
        ull t;
        t = pack2(wa.x, wa.x); fma2(acc[0][0], xv.x, t); fma2(acc[0][1], xv.y, t);
        t = pack2(wa.y, wa.y); fma2(acc[1][0], xv.x, t); fma2(acc[1][1], xv.y, t);
        t = pack2(wa.z, wa.z); fma2(acc[2][0], xv.x, t); fma2(acc[2][1], xv.y, t);
        t = pack2(wa.w, wa.w); fma2(acc[3][0], xv.x, t); fma2(acc[3][1], xv.y, t);
        t = pack2(wb.x, wb.x); fma2(acc[4][0], xv.x, t); fma2(acc[4][1], xv.y, t);
        t = pack2(wb.y, wb.y); fma2(acc[5][0], xv.x, t); fma2(acc[5][1], xv.y, t);
        t = pack2(wb.z, wb.z); fma2(acc[6][0], xv.x, t); fma2(acc[6][1], xv.y, t);
    }

    float* dst = g_wgt + ((size_t)b * 784 + k0) * HW + pt * 128 + lane * 4;
    #pragma unroll
    for (int i = 0; i < 7; i++)
        *(ulonglong2*)(dst + (size_t)i * HW) = make_ulonglong2(acc[i][0], acc[i][1]);
}

// ---------------------------------------------------------------------------
// Kernel 2b: 7x7 dynamic aggregation + residual (unchanged from R7).
// Tile = 16x8 px, 256 threads, 47.9 KB smem, 4 CTA/SM.
// ---------------------------------------------------------------------------
#define FRS 16
#define FCH 356

__global__ __launch_bounds__(256, 4)
void agg_kernel(const float* __restrict__ feat,
                float* __restrict__ out)
{
    extern __shared__ float smem[];
    float* f_sh   = smem;               // 16*356 f   22784 B
    float* wgt_sh = smem + 16 * FCH;    // [49][128]  25088 B

    const int tid  = threadIdx.x;
    const int g    = blockIdx.x;
    const int tile = blockIdx.y;
    const int b    = blockIdx.z;
    const int y0 = (tile >> 3) * 16;
    const int x0 = (tile & 7) * 8;
    const int w    = tid >> 5;
    const int lane = tid & 31;

    {
        const float* src0 = g_wgt + ((size_t)b * 784 + g * 49) * HW + y0 * WDIM + x0;
        for (int i = tid; i < 1568; i += 256) {
            int k = i >> 5, rem = i & 31;
            int row = rem >> 1, half = rem & 1;
            cp_async16(smem_u32(wgt_sh + k * 128 + row * 8 + half * 4),
                       src0 + (size_t)k * HW + row * WDIM + half * 4);
        }
    }
    {
        const float* fch0 = feat + (size_t)(b * 256 + g * 16) * HW;
        for (int i = tid; i < 1408; i += 256) {
            int c   = i / 88;
            int rem = i - c * 88;
            int yy  = rem >> 2;
            int q   = rem & 3;
            int gy  = y0 + yy - 3;
            int gx0 = x0 - 4 + q * 4;
            bool ok = ((unsigned)gy < 64u) && ((unsigned)gx0 <= 60u);
            const float* src = fch0 + (size_t)c * HW + (ok ? gy * WDIM + gx0 : 0);
            cp_async16z(smem_u32(f_sh + c * FCH + yy * FRS + q * 4), src, ok ? 16 : 0);
        }
    }
    cp_commit();
    asm volatile("cp.async.wait_group 0;");
    __syncthreads();

    {
        const int rowA = 2 * w + (lane >> 4);
        const int c    = lane & 15;

        const float* fbase = f_sh + c * FCH;
        const float* wbase = wgt_sh + rowA * 8;

        ull accp[4] = {0ull, 0ull, 0ull, 0ull};

        #pragma unroll 1
        for (int di = 0; di < 7; di++) {
            const float* frow = fbase + (rowA + di) * FRS;
            float4 A = *(const float4*)(frow);
            float4 B = *(const float4*)(frow + 4);
            float4 C = *(const float4*)(frow + 8);
            float4 D = *(const float4*)(frow + 12);
            ull fra[7];
            fra[1] = pack2(A.z, A.w); fra[2] = pack2(B.x, B.y);
            fra[3] = pack2(B.z, B.w); fra[4] = pack2(C.x, C.y);
            fra[5] = pack2(C.z, C.w); fra[6] = pack2(D.x, D.y);
            ull frb[7];
            frb[0] = pack2(A.y, A.z); frb[1] = pack2(A.w, B.x);
            frb[2] = pack2(B.y, B.z); frb[3] = pack2(B.w, C.x);
            frb[4] = pack2(C.y, C.z); frb[5] = pack2(C.w, D.x);
            frb[6] = pack2(D.y, D.z);

            #pragma unroll
            for (int dj = 0; dj < 7; dj += 2) {
                int k = di * 7 + dj;
                ulonglong2 wv01 = *(const ulonglong2*)(wbase + k * 128);
                ulonglong2 wv23 = *(const ulonglong2*)(wbase + k * 128 + 4);
                int s = dj >> 1;
                fma2(accp[0], wv01.x, frb[s]);
                fma2(accp[1], wv01.y, frb[s + 1]);
                fma2(accp[2], wv23.x, frb[s + 2]);
                fma2(accp[3], wv23.y, frb[s + 3]);
            }
            #pragma unroll
            for (int dj = 1; dj < 7; dj += 2) {
                int k = di * 7 + dj;
                ulonglong2 wv01 = *(const ulonglong2*)(wbase + k * 128);
                ulonglong2 wv23 = *(const ulonglong2*)(wbase + k * 128 + 4);
                int s = (dj + 1) >> 1;
                fma2(accp[0], wv01.x, fra[s]);
                fma2(accp[1], wv01.y, fra[s + 1]);
                fma2(accp[2], wv23.x, fra[s + 2]);
                fma2(accp[3], wv23.y, fra[s + 3]);
            }
        }

        float acc[8];
        unpack2(accp[0], acc[0], acc[1]);
        unpack2(accp[1], acc[2], acc[3]);
        unpack2(accp[2], acc[4], acc[5]);
        unpack2(accp[3], acc[6], acc[7]);
        #pragma unroll
        for (int j = 0; j < 8; j++)
            acc[j] += fbase[(rowA + 3) * FRS + j + 4];

        float* op = &out[(size_t)(b * 256 + g * 16 + c) * HW + (y0 + rowA) * WDIM + x0];
        *(float4*)(op)     = make_float4(acc[0], acc[1], acc[2], acc[3]);
        *(float4*)(op + 4) = make_float4(acc[4], acc[5], acc[6], acc[7]);
    }
}

// ---------------------------------------------------------------------------
extern "C" void kernel_launch(void* const* d_in, const int* in_sizes, int n_in,
                              void* d_out, int out_size)
{
    const float* feat  = (const float*)d_in[0];
    const float* guide = (const float*)d_in[1];
    const float* w1    = (const float*)d_in[2];
    const float* gamma = (const float*)d_in[3];
    const float* beta  = (const float*)d_in[4];
    const float* mean  = (const float*)d_in[5];
    const float* var   = (const float*)d_in[6];
    const float* w2    = (const float*)d_in[7];
    const float* b2    = (const float*)d_in[8];
    float* out = (float*)d_out;

    prep_kernel<<<224, 256>>>(w1, gamma, beta, mean, var, w2);

    const int c1_smem = (16384 + 2 * C1G) * 4;            // 100352
    cudaFuncSetAttribute(conv1_kernel,
                         cudaFuncAttributeMaxDynamicSharedMemorySize, c1_smem);
    conv1_kernel<<<dim3(64, 4), 256, c1_smem>>>(guide);

    const int g_smem = (64 * 128 + 64 * 128) * 4;         // 65536
    cudaFuncSetAttribute(gemm2_kernel,
                         cudaFuncAttributeMaxDynamicSharedMemorySize, g_smem);
    gemm2_kernel<<<dim3(7, 32, 4), 512, g_smem>>>(b2);

    const int a_smem = (16 * FCH + 49 * 128) * 4;         // 47872
    cudaFuncSetAttribute(agg_kernel,
                         cudaFuncAttributeMaxDynamicSharedMemorySize, a_smem);
    agg_kernel<<<dim3(16, 32, 4), 256, a_smem>>>(feat, out);
}

// round 12
// speedup vs baseline: 1.7712x; 1.3366x over previous
#include <cuda_runtime.h>
#include <cuda_fp16.h>
#include <cstdint>

// Problem constants: B=4, C=256, H=W=64, K=7, GROUPS=16, GC=16, CR=64
#define HW   4096
#define WDIM 64

typedef unsigned long long ull;

// Scratch (static device globals — no allocs):
__device__ float  g_wgt[4 * 784 * 4096];   // dynamic weights (fp32)    51.4 MB
__device__ float  g_w1f[64 * 256];         // w1 transposed [r][m], BN-folded
__device__ float  g_b1f[64];               // folded conv1 bias
__device__ __half g_xh [4 * 32 * 128 * 64];// x fp16, SW128-swizzled 128px x 64r tiles
__device__ __half g_w2h[7 * 112 * 64];     // w2 fp16, SW128-swizzled 112k x 64r tiles

__device__ __forceinline__ ull pack2(float lo, float hi) {
    ull r; asm("mov.b64 %0, {%1, %2};" : "=l"(r) : "f"(lo), "f"(hi)); return r;
}
__device__ __forceinline__ void unpack2(ull v, float &lo, float &hi) {
    asm("mov.b64 {%0, %1}, %2;" : "=f"(lo), "=f"(hi) : "l"(v));
}
__device__ __forceinline__ void fma2(ull &d, ull a, ull b) {
    asm("fma.rn.f32x2 %0, %1, %2, %0;" : "+l"(d) : "l"(a), "l"(b));
}
__device__ __forceinline__ unsigned smem_u32(const void* p) {
    return (unsigned)__cvta_generic_to_shared(p);
}
__device__ __forceinline__ void cp_async16(unsigned dst, const void* src) {
    asm volatile("cp.async.cg.shared.global [%0], [%1], 16;" :: "r"(dst), "l"(src));
}
__device__ __forceinline__ void cp_async16z(unsigned dst, const void* src, int sz) {
    asm volatile("cp.async.cg.shared.global [%0], [%1], 16, %2;"
                 :: "r"(dst), "l"(src), "r"(sz));
}
__device__ __forceinline__ void cp_async4(unsigned dst, const void* src) {
    asm volatile("cp.async.ca.shared.global [%0], [%1], 4;" :: "r"(dst), "l"(src));
}
__device__ __forceinline__ void cp_commit() {
    asm volatile("cp.async.commit_group;");
}

// ---- mma.sync (sm_80-era path: legal on plain sm_103 PTX target) ----
__device__ __forceinline__ void ldsm4(uint32_t* r, uint32_t addr) {
    asm volatile("ldmatrix.sync.aligned.m8n8.x4.shared.b16 {%0,%1,%2,%3}, [%4];"
                 : "=r"(r[0]), "=r"(r[1]), "=r"(r[2]), "=r"(r[3]) : "r"(addr));
}
__device__ __forceinline__ void mma16816(float* c, const uint32_t* a,
                                         uint32_t b0, uint32_t b1) {
    asm volatile("mma.sync.aligned.m16n8k16.row.col.f32.f16.f16.f32 "
                 "{%0,%1,%2,%3}, {%4,%5,%6,%7}, {%8,%9}, {%0,%1,%2,%3};"
                 : "+f"(c[0]), "+f"(c[1]), "+f"(c[2]), "+f"(c[3])
                 : "r"(a[0]), "r"(a[1]), "r"(a[2]), "r"(a[3]), "r"(b0), "r"(b1));
}

static __device__ __forceinline__ uint32_t sw128(uint32_t off) {
    return off ^ ((off >> 3) & 0x70);
}

// ---------------------------------------------------------------------------
// Kernel 0: prep — fold BN into w1f; w2 -> fp16 SW128 tiles.
// ---------------------------------------------------------------------------
__global__ __launch_bounds__(256)
void prep_kernel(const float* __restrict__ w1,
                 const float* __restrict__ gamma,
                 const float* __restrict__ beta,
                 const float* __restrict__ mean,
                 const float* __restrict__ var,
                 const float* __restrict__ w2)
{
    int idx = blockIdx.x * 256 + threadIdx.x;

    if (idx < 64) {
        float inv = gamma[idx] * rsqrtf(var[idx] + 1e-5f);
        g_b1f[idx] = beta[idx] - mean[idx] * inv;
    }
    if (idx < 64 * 256) {                 // w1f[r][m] = w1[m][r] * inv[m]
        int r = idx >> 6, m = idx & 63;
        float inv = gamma[m] * rsqrtf(var[m] + 1e-5f);
        g_w1f[idx] = w1[m * 256 + r] * inv;
    }
    if (idx < 7 * 112 * 64) {             // w2h tile kb: [n=112][r=64] fp16, SW128
        int kb = idx / (112 * 64);
        int rem = idx - kb * 112 * 64;
        int n = rem >> 6, r = rem & 63;
        float v = w2[(kb * 112 + n) * 64 + r];
        uint32_t off = sw128((uint32_t)(n * 128 + r * 2));
        g_w2h[kb * 7168 + (off >> 1)] = __float2half(v);
    }
}

// ---------------------------------------------------------------------------
// Kernel 1: conv1 (1x1, 256->64, BN folded) + ReLU -> g_xh (fp16, swizzled)
// 64-px tiles, 256 threads, grid (64,4), 2 CTA/SM.
// ---------------------------------------------------------------------------
#define C1G 4352   // 64*68 floats per guide buffer

__global__ __launch_bounds__(256, 2)
void conv1_kernel(const float* __restrict__ guide)
{
    extern __shared__ float csm[];
    float* w1s = csm;                                    // [256 r][64 m] 64 KB
    float* gb[2] = { csm + 16384, csm + 16384 + C1G };

    const int tid   = threadIdx.x;
    const int b     = blockIdx.y;
    const int gpix0 = blockIdx.x * 64;
    const int mq = tid >> 4, pq = tid & 15;
    const int m0 = mq * 4,   p0 = pq * 4;

    #pragma unroll
    for (int i = tid; i < 4096; i += 256)
        cp_async16(smem_u32(w1s + i * 4), g_w1f + i * 4);
    #pragma unroll
    for (int i = tid; i < 1024; i += 256) {
        int rr = i >> 4, px4 = (i & 15) * 4;
        cp_async16(smem_u32(gb[0] + rr * 68 + px4),
                   guide + (size_t)(b * 256 + rr) * HW + gpix0 + px4);
    }
    cp_commit();
    #pragma unroll
    for (int i = tid; i < 1024; i += 256) {
        int rr = i >> 4, px4 = (i & 15) * 4;
        cp_async16(smem_u32(gb[1] + rr * 68 + px4),
                   guide + (size_t)(b * 256 + 64 + rr) * HW + gpix0 + px4);
    }
    cp_commit();

    ull acc[4][2];
    #pragma unroll
    for (int i = 0; i < 4; i++) {
        float bv = g_b1f[m0 + i];
        ull bp = pack2(bv, bv);
        acc[i][0] = bp; acc[i][1] = bp;
    }

    for (int blk = 0; blk < 4; blk++) {
        if (blk < 3) asm volatile("cp.async.wait_group 1;");
        else         asm volatile("cp.async.wait_group 0;");
        __syncthreads();

        const float* wb  = w1s + blk * 64 * 64;
        const float* gsh = gb[blk & 1];

        #pragma unroll 8
        for (int rr = 0; rr < 64; rr++) {
            float4 w4 = *(const float4*)&wb[rr * 64 + m0];
            ulonglong2 xv = *(const ulonglong2*)&gsh[rr * 68 + p0];
            ull wp;
            wp = pack2(w4.x, w4.x); fma2(acc[0][0], xv.x, wp); fma2(acc[0][1], xv.y, wp);
            wp = pack2(w4.y, w4.y); fma2(acc[1][0], xv.x, wp); fma2(acc[1][1], xv.y, wp);
            wp = pack2(w4.z, w4.z); fma2(acc[2][0], xv.x, wp); fma2(acc[2][1], xv.y, wp);
            wp = pack2(w4.w, w4.w); fma2(acc[3][0], xv.x, wp); fma2(acc[3][1], xv.y, wp);
        }
        __syncthreads();

        if (blk + 2 < 4) {
            float* dstb = gb[blk & 1];
            #pragma unroll
            for (int i = tid; i < 1024; i += 256) {
                int rr = i >> 4, px4 = (i & 15) * 4;
                cp_async16(smem_u32(dstb + rr * 68 + px4),
                           guide + (size_t)(b * 256 + (blk + 2) * 64 + rr) * HW + gpix0 + px4);
            }
            cp_commit();
        }
    }

    // epilogue: relu, write fp16 transposed+swizzled tiles x_t[px][r]
    float vv[4][4];
    #pragma unroll
    for (int i = 0; i < 4; i++) {
        unpack2(acc[i][0], vv[i][0], vv[i][1]);
        unpack2(acc[i][1], vv[i][2], vv[i][3]);
        #pragma unroll
        for (int j = 0; j < 4; j++) vv[i][j] = fmaxf(vv[i][j], 0.f);
    }
    #pragma unroll
    for (int j = 0; j < 4; j++) {
        int px  = gpix0 + p0 + j;
        int t   = b * 32 + (px >> 7);
        int row = px & 127;
        uint32_t off = sw128((uint32_t)(row * 128 + m0 * 2));
        __half2* dst = (__half2*)(g_xh + (size_t)t * 8192 + (off >> 1));
        dst[0] = __floats2half2_rn(vv[0][j], vv[1][j]);
        dst[1] = __floats2half2_rn(vv[2][j], vv[3][j]);
    }
}

// ---------------------------------------------------------------------------
// Kernel 2a: conv2 GEMM via ldmatrix + mma.sync.m16n8k16 (fp16 in, fp32 acc).
// D[128 px, 112 k] = A[128,64] * B[112,64]^T, TN layout (both k-major).
// 256 threads (8 warps, warp = 16-px m-tile); 31.7 KB smem -> ~6 CTA/SM.
// Grid (7 kb, 32 pt, 4 b) = 896 CTAs. Bias folded into accumulator init.
// ---------------------------------------------------------------------------
#define G2_BIAS  0
#define G2_A     1024
#define G2_B     (1024 + 16384)              // 17408
#define G2_SIZE  (17408 + 14336)             // 31744

__global__ __launch_bounds__(256)
void gemm2_mma(const float* __restrict__ b2)
{
    extern __shared__ char smem[];
    const unsigned sb = smem_u32(smem);
    const int tid  = threadIdx.x;
    const int w    = tid >> 5;
    const int lane = tid & 31;
    const int kb = blockIdx.x, pt = blockIdx.y, b = blockIdx.z;

    // stage A (16 KB), B (14 KB), bias — all linear (pre-swizzled in global)
    {
        const __half* asrc = g_xh + (size_t)(b * 32 + pt) * 8192;
        #pragma unroll
        for (int i = tid; i < 1024; i += 256)
            cp_async16(sb + G2_A + i * 16, asrc + i * 8);
        const __half* bsrc = g_w2h + kb * 7168;
        #pragma unroll
        for (int i = tid; i < 896; i += 256)
            cp_async16(sb + G2_B + i * 16, bsrc + i * 8);
        if (tid < 112)
            cp_async4(sb + G2_BIAS + tid * 4, b2 + kb * 112 + tid);
    }
    cp_commit();
    asm volatile("cp.async.wait_group 0;");
    __syncthreads();

    // accumulators seeded with bias: cols of tile nt are k = nt*8 + (lane&3)*2 + {0,1}
    const float* bias_s = (const float*)smem;
    float acc[14][4];
    {
        int kc = (lane & 3) * 2;
        #pragma unroll
        for (int nt = 0; nt < 14; nt++) {
            float be = bias_s[nt * 8 + kc];
            float bo = bias_s[nt * 8 + kc + 1];
            acc[nt][0] = be; acc[nt][1] = bo;
            acc[nt][2] = be; acc[nt][3] = bo;
        }
    }

    // ldmatrix row/colblock for this lane (same pattern for A and B)
    const int lrow = lane & 15;
    const int lcb  = lane >> 4;

    #pragma unroll
    for (int ks = 0; ks < 4; ks++) {
        uint32_t a[4];
        {
            uint32_t off = sw128((uint32_t)((w * 16 + lrow) * 128 + ks * 32 + lcb * 16));
            ldsm4(a, sb + G2_A + off);
        }
        #pragma unroll
        for (int ntp = 0; ntp < 7; ntp++) {
            uint32_t bf[4];
            uint32_t off = sw128((uint32_t)((ntp * 16 + lrow) * 128 + ks * 32 + lcb * 16));
            ldsm4(bf, sb + G2_B + off);
            mma16816(acc[2 * ntp],     a, bf[0], bf[2]);   // n-rows 0-7  of pair
            mma16816(acc[2 * ntp + 1], a, bf[1], bf[3]);   // n-rows 8-15 of pair
        }
    }

    // store: thread holds (px = w*16 + lane/4 (+8), k = nt*8 + (lane&3)*2 (+1))
    // 8-lane groups write 8 consecutive px -> full 32B sectors.
    {
        const int pxl = w * 16 + (lane >> 2);
        const int kc  = (lane & 3) * 2;
        float* base = g_wgt + ((size_t)b * 784 + kb * 112) * HW + pt * 128 + pxl;
        #pragma unroll
        for (int nt = 0; nt < 14; nt++) {
            float* d0 = base + (size_t)(nt * 8 + kc) * HW;
            d0[0]           = acc[nt][0];
            d0[HW]          = acc[nt][1];
            d0[8]           = acc[nt][2];
            d0[HW + 8]      = acc[nt][3];
        }
    }
}

// ---------------------------------------------------------------------------
// Kernel 2b: 7x7 dynamic aggregation + residual (unchanged, proven).
// ---------------------------------------------------------------------------
#define FRS 16
#define FCH 356

__global__ __launch_bounds__(256, 4)
void agg_kernel(const float* __restrict__ feat,
                float* __restrict__ out)
{
    extern __shared__ float smemf[];
    float* f_sh   = smemf;               // 16*356 f   22784 B
    float* wgt_sh = smemf + 16 * FCH;    // [49][128]  25088 B

    const int tid  = threadIdx.x;
    const int g    = blockIdx.x;
    const int tile = blockIdx.y;
    const int b    = blockIdx.z;
    const int y0 = (tile >> 3) * 16;
    const int x0 = (tile & 7) * 8;
    const int w    = tid >> 5;
    const int lane = tid & 31;

    {
        const float* src0 = g_wgt + ((size_t)b * 784 + g * 49) * HW + y0 * WDIM + x0;
        for (int i = tid; i < 1568; i += 256) {
            int k = i >> 5, rem = i & 31;
            int row = rem >> 1, half = rem & 1;
            cp_async16(smem_u32(wgt_sh + k * 128 + row * 8 + half * 4),
                       src0 + (size_t)k * HW + row * WDIM + half * 4);
        }
    }
    {
        const float* fch0 = feat + (size_t)(b * 256 + g * 16) * HW;
        for (int i = tid; i < 1408; i += 256) {
            int c   = i / 88;
            int rem = i - c * 88;
            int yy  = rem >> 2;
            int q   = rem & 3;
            int gy  = y0 + yy - 3;
            int gx0 = x0 - 4 + q * 4;
            bool ok = ((unsigned)gy < 64u) && ((unsigned)gx0 <= 60u);
            const float* src = fch0 + (size_t)c * HW + (ok ? gy * WDIM + gx0 : 0);
            cp_async16z(smem_u32(f_sh + c * FCH + yy * FRS + q * 4), src, ok ? 16 : 0);
        }
    }
    cp_commit();
    asm volatile("cp.async.wait_group 0;");
    __syncthreads();

    {
        const int rowA = 2 * w + (lane >> 4);
        const int c    = lane & 15;

        const float* fbase = f_sh + c * FCH;
        const float* wbase = wgt_sh + rowA * 8;

        ull accp[4] = {0ull, 0ull, 0ull, 0ull};

        #pragma unroll 1
        for (int di = 0; di < 7; di++) {
            const float* frow = fbase + (rowA + di) * FRS;
            float4 A = *(const float4*)(frow);
            float4 B = *(const float4*)(frow + 4);
            float4 C = *(const float4*)(frow + 8);
            float4 D = *(const float4*)(frow + 12);
            ull fra[7];
            fra[1] = pack2(A.z, A.w); fra[2] = pack2(B.x, B.y);
            fra[3] = pack2(B.z, B.w); fra[4] = pack2(C.x, C.y);
            fra[5] = pack2(C.z, C.w); fra[6] = pack2(D.x, D.y);
            ull frb[7];
            frb[0] = pack2(A.y, A.z); frb[1] = pack2(A.w, B.x);
            frb[2] = pack2(B.y, B.z); frb[3] = pack2(B.w, C.x);
            frb[4] = pack2(C.y, C.z); frb[5] = pack2(C.w, D.x);
            frb[6] = pack2(D.y, D.z);

            #pragma unroll
            for (int dj = 0; dj < 7; dj += 2) {
                int k = di * 7 + dj;
                ulonglong2 wv01 = *(const ulonglong2*)(wbase + k * 128);
                ulonglong2 wv23 = *(const ulonglong2*)(wbase + k * 128 + 4);
                int s = dj >> 1;
                fma2(accp[0], wv01.x, frb[s]);
                fma2(accp[1], wv01.y, frb[s + 1]);
                fma2(accp[2], wv23.x, frb[s + 2]);
                fma2(accp[3], wv23.y, frb[s + 3]);
            }
            #pragma unroll
            for (int dj = 1; dj < 7; dj += 2) {
                int k = di * 7 + dj;
                ulonglong2 wv01 = *(const ulonglong2*)(wbase + k * 128);
                ulonglong2 wv23 = *(const ulonglong2*)(wbase + k * 128 + 4);
                int s = (dj + 1) >> 1;
                fma2(accp[0], wv01.x, fra[s]);
                fma2(accp[1], wv01.y, fra[s + 1]);
                fma2(accp[2], wv23.x, fra[s + 2]);
                fma2(accp[3], wv23.y, fra[s + 3]);
            }
        }

        float acc[8];
        unpack2(accp[0], acc[0], acc[1]);
        unpack2(accp[1], acc[2], acc[3]);
        unpack2(accp[2], acc[4], acc[5]);
        unpack2(accp[3], acc[6], acc[7]);
        #pragma unroll
        for (int j = 0; j < 8; j++)
            acc[j] += fbase[(rowA + 3) * FRS + j + 4];

        float* op = &out[(size_t)(b * 256 + g * 16 + c) * HW + (y0 + rowA) * WDIM + x0];
        *(float4*)(op)     = make_float4(acc[0], acc[1], acc[2], acc[3]);
        *(float4*)(op + 4) = make_float4(acc[4], acc[5], acc[6], acc[7]);
    }
}

// ---------------------------------------------------------------------------
extern "C" void kernel_launch(void* const* d_in, const int* in_sizes, int n_in,
                              void* d_out, int out_size)
{
    const float* feat  = (const float*)d_in[0];
    const float* guide = (const float*)d_in[1];
    const float* w1    = (const float*)d_in[2];
    const float* gamma = (const float*)d_in[3];
    const float* beta  = (const float*)d_in[4];
    const float* mean  = (const float*)d_in[5];
    const float* var   = (const float*)d_in[6];
    const float* w2    = (const float*)d_in[7];
    const float* b2    = (const float*)d_in[8];
    float* out = (float*)d_out;

    prep_kernel<<<224, 256>>>(w1, gamma, beta, mean, var, w2);

    const int c1_smem = (16384 + 2 * C1G) * 4;            // 100352
    cudaFuncSetAttribute(conv1_kernel,
                         cudaFuncAttributeMaxDynamicSharedMemorySize, c1_smem);
    conv1_kernel<<<dim3(64, 4), 256, c1_smem>>>(guide);

    cudaFuncSetAttribute(gemm2_mma,
                         cudaFuncAttributeMaxDynamicSharedMemorySize, G2_SIZE);
    gemm2_mma<<<dim3(7, 32, 4), 256, G2_SIZE>>>(b2);

    const int a_smem = (16 * FCH + 49 * 128) * 4;         // 47872
    cudaFuncSetAttribute(agg_kernel,
                         cudaFuncAttributeMaxDynamicSharedMemorySize, a_smem);
    agg_kernel<<<dim3(16, 32, 4), 256, a_smem>>>(feat, out);
}

// round 13
// speedup vs baseline: 2.0719x; 1.1698x over previous
#include <cuda_runtime.h>
#include <cuda_fp16.h>
#include <cstdint>

// Problem constants: B=4, C=256, H=W=64, K=7, GROUPS=16, GC=16, CR=64
#define HW   4096
#define WDIM 64

typedef unsigned long long ull;

// Scratch (static device globals — no allocs):
__device__ float  g_w1f[64 * 256];          // w1 transposed [r][m], BN-folded
__device__ float  g_b1f[64];                // folded conv1 bias
__device__ __half g_xh [4 * 32 * 128 * 64]; // x fp16, SW128 tiles keyed by spatial 16x8 tile
__device__ __half g_w2g[16 * 64 * 64];      // w2 fp16 per-group [64k pad][64r], SW128

__device__ __forceinline__ ull pack2(float lo, float hi) {
    ull r; asm("mov.b64 %0, {%1, %2};" : "=l"(r) : "f"(lo), "f"(hi)); return r;
}
__device__ __forceinline__ void unpack2(ull v, float &lo, float &hi) {
    asm("mov.b64 {%0, %1}, %2;" : "=f"(lo), "=f"(hi) : "l"(v));
}
__device__ __forceinline__ void fma2(ull &d, ull a, ull b) {
    asm("fma.rn.f32x2 %0, %1, %2, %0;" : "+l"(d) : "l"(a), "l"(b));
}
__device__ __forceinline__ unsigned smem_u32(const void* p) {
    return (unsigned)__cvta_generic_to_shared(p);
}
__device__ __forceinline__ void cp_async16(unsigned dst, const void* src) {
    asm volatile("cp.async.cg.shared.global [%0], [%1], 16;" :: "r"(dst), "l"(src));
}
__device__ __forceinline__ void cp_async16z(unsigned dst, const void* src, int sz) {
    asm volatile("cp.async.cg.shared.global [%0], [%1], 16, %2;"
                 :: "r"(dst), "l"(src), "r"(sz));
}
__device__ __forceinline__ void cp_async4(unsigned dst, const void* src) {
    asm volatile("cp.async.ca.shared.global [%0], [%1], 4;" :: "r"(dst), "l"(src));
}
__device__ __forceinline__ void cp_commit() {
    asm volatile("cp.async.commit_group;");
}

// ---- mma.sync (sm_80-era path: legal on plain sm_103 PTX target) ----
__device__ __forceinline__ void ldsm4(uint32_t* r, uint32_t addr) {
    asm volatile("ldmatrix.sync.aligned.m8n8.x4.shared.b16 {%0,%1,%2,%3}, [%4];"
                 : "=r"(r[0]), "=r"(r[1]), "=r"(r[2]), "=r"(r[3]) : "r"(addr));
}
__device__ __forceinline__ void mma16816(float* c, const uint32_t* a,
                                         uint32_t b0, uint32_t b1) {
    asm volatile("mma.sync.aligned.m16n8k16.row.col.f32.f16.f16.f32 "
                 "{%0,%1,%2,%3}, {%4,%5,%6,%7}, {%8,%9}, {%0,%1,%2,%3};"
                 : "+f"(c[0]), "+f"(c[1]), "+f"(c[2]), "+f"(c[3])
                 : "r"(a[0]), "r"(a[1]), "r"(a[2]), "r"(a[3]), "r"(b0), "r"(b1));
}

static __device__ __forceinline__ uint32_t sw128(uint32_t off) {
    return off ^ ((off >> 3) & 0x70);
}

// ---------------------------------------------------------------------------
// Kernel 0: prep — fold BN into w1f; w2 -> fp16 per-group SW128 tiles (k pad 64).
// Grid 256 x 256.
// ---------------------------------------------------------------------------
__global__ __launch_bounds__(256)
void prep_kernel(const float* __restrict__ w1,
                 const float* __restrict__ gamma,
                 const float* __restrict__ beta,
                 const float* __restrict__ mean,
                 const float* __restrict__ var,
                 const float* __restrict__ w2)
{
    int idx = blockIdx.x * 256 + threadIdx.x;

    if (idx < 64) {
        float inv = gamma[idx] * rsqrtf(var[idx] + 1e-5f);
        g_b1f[idx] = beta[idx] - mean[idx] * inv;
    }
    if (idx < 64 * 256) {                 // w1f[r][m] = w1[m][r] * inv[m]
        int r = idx >> 6, m = idx & 63;
        float inv = gamma[m] * rsqrtf(var[m] + 1e-5f);
        g_w1f[idx] = w1[m * 256 + r] * inv;
    }
    if (idx < 16 * 64 * 64) {             // per-group B tile [k pad 64][r 64], SW128
        int g = idx >> 12;
        int rem = idx & 4095;
        int k = rem >> 6, r = rem & 63;
        float v = (k < 49) ? w2[(g * 49 + k) * 64 + r] : 0.f;
        uint32_t off = sw128((uint32_t)(k * 128 + r * 2));
        g_w2g[g * 4096 + (off >> 1)] = __float2half(v);
    }
}

// ---------------------------------------------------------------------------
// Kernel 1: conv1 (1x1, 256->64, BN folded) + ReLU -> g_xh (fp16, swizzled,
// spatial-tile-major: tile = 16x8 block, inner = (y&15)*8 + (x&7)).
// 64-px tiles (one image row per CTA), 256 threads, grid (64,4), 2 CTA/SM.
// ---------------------------------------------------------------------------
#define C1G 4352   // 64*68 floats per guide buffer

__global__ __launch_bounds__(256, 2)
void conv1_kernel(const float* __restrict__ guide)
{
    extern __shared__ float csm[];
    float* w1s = csm;                                    // [256 r][64 m] 64 KB
    float* gb[2] = { csm + 16384, csm + 16384 + C1G };

    const int tid   = threadIdx.x;
    const int b     = blockIdx.y;
    const int yrow  = blockIdx.x;                 // image row
    const int gpix0 = yrow * 64;
    const int mq = tid >> 4, pq = tid & 15;
    const int m0 = mq * 4,   p0 = pq * 4;

    #pragma unroll
    for (int i = tid; i < 4096; i += 256)
        cp_async16(smem_u32(w1s + i * 4), g_w1f + i * 4);
    #pragma unroll
    for (int i = tid; i < 1024; i += 256) {
        int rr = i >> 4, px4 = (i & 15) * 4;
        cp_async16(smem_u32(gb[0] + rr * 68 + px4),
                   guide + (size_t)(b * 256 + rr) * HW + gpix0 + px4);
    }
    cp_commit();
    #pragma unroll
    for (int i = tid; i < 1024; i += 256) {
        int rr = i >> 4, px4 = (i & 15) * 4;
        cp_async16(smem_u32(gb[1] + rr * 68 + px4),
                   guide + (size_t)(b * 256 + 64 + rr) * HW + gpix0 + px4);
    }
    cp_commit();

    ull acc[4][2];
    #pragma unroll
    for (int i = 0; i < 4; i++) {
        float bv = g_b1f[m0 + i];
        ull bp = pack2(bv, bv);
        acc[i][0] = bp; acc[i][1] = bp;
    }

    for (int blk = 0; blk < 4; blk++) {
        if (blk < 3) asm volatile("cp.async.wait_group 1;");
        else         asm volatile("cp.async.wait_group 0;");
        __syncthreads();

        const float* wb  = w1s + blk * 64 * 64;
        const float* gsh = gb[blk & 1];

        #pragma unroll 8
        for (int rr = 0; rr < 64; rr++) {
            float4 w4 = *(const float4*)&wb[rr * 64 + m0];
            ulonglong2 xv = *(const ulonglong2*)&gsh[rr * 68 + p0];
            ull wp;
            wp = pack2(w4.x, w4.x); fma2(acc[0][0], xv.x, wp); fma2(acc[0][1], xv.y, wp);
            wp = pack2(w4.y, w4.y); fma2(acc[1][0], xv.x, wp); fma2(acc[1][1], xv.y, wp);
            wp = pack2(w4.z, w4.z); fma2(acc[2][0], xv.x, wp); fma2(acc[2][1], xv.y, wp);
            wp = pack2(w4.w, w4.w); fma2(acc[3][0], xv.x, wp); fma2(acc[3][1], xv.y, wp);
        }
        __syncthreads();

        if (blk + 2 < 4) {
            float* dstb = gb[blk & 1];
            #pragma unroll
            for (int i = tid; i < 1024; i += 256) {
                int rr = i >> 4, px4 = (i & 15) * 4;
                cp_async16(smem_u32(dstb + rr * 68 + px4),
                           guide + (size_t)(b * 256 + (blk + 2) * 64 + rr) * HW + gpix0 + px4);
            }
            cp_commit();
        }
    }

    // epilogue: relu, write fp16 spatial-tile-major swizzled tiles
    float vv[4][4];
    #pragma unroll
    for (int i = 0; i < 4; i++) {
        unpack2(acc[i][0], vv[i][0], vv[i][1]);
        unpack2(acc[i][1], vv[i][2], vv[i][3]);
        #pragma unroll
        for (int j = 0; j < 4; j++) vv[i][j] = fmaxf(vv[i][j], 0.f);
    }
    #pragma unroll
    for (int j = 0; j < 4; j++) {
        int col  = p0 + j;                              // 0..63
        int tile = (yrow >> 4) * 8 + (col >> 3);        // 0..31
        int inner = (yrow & 15) * 8 + (col & 7);        // 0..127
        uint32_t off = sw128((uint32_t)(inner * 128 + m0 * 2));
        __half2* dst = (__half2*)(g_xh + (size_t)(b * 32 + tile) * 8192 + (off >> 1));
        dst[0] = __floats2half2_rn(vv[0][j], vv[1][j]);
        dst[1] = __floats2half2_rn(vv[2][j], vv[3][j]);
    }
}

// ---------------------------------------------------------------------------
// Kernel 2: FUSED conv2-MMA + 7x7 dynamic aggregation + residual.
// CTA = (group, 16x8 tile, batch); 256 threads (8 warps); ~74.3 KB smem,
// 3 CTA/SM; grid (16, 32, 4) = 2048. The 51 MB weight tensor never exists.
//   MMA: D[128 inner-px, 64 k(pad)] = A[128,64] * B[64,64]^T, bias-seeded.
//   STS fragments -> wgt_sh[k][inner] with row stride 132 (conflict-free).
//   Agg: proven R12 phase, wgt row stride 132.
// ---------------------------------------------------------------------------
#define F_BIAS 0
#define F_A    1024                      // 16384 B
#define F_B    17408                     // 8192 B
#define F_F    25600                     // 16*356*4 = 22784 B
#define F_WGT  48384                     // 49*132*4 = 25872 B
#define F_SIZE 74256
#define FRS 16
#define FCH 356
#define WGS 132                          // wgt_sh row stride (floats)

__global__ __launch_bounds__(256, 3)
void fused2_kernel(const float* __restrict__ feat,
                   const float* __restrict__ b2,
                   float* __restrict__ out)
{
    extern __shared__ char smem[];
    const unsigned sb = smem_u32(smem);
    float* f_sh   = (float*)(smem + F_F);
    float* wgt_sh = (float*)(smem + F_WGT);
    const float* bias_s = (const float*)smem;

    const int tid  = threadIdx.x;
    const int g    = blockIdx.x;
    const int tile = blockIdx.y;
    const int b    = blockIdx.z;
    const int y0 = (tile >> 3) * 16;
    const int x0 = (tile & 7) * 8;
    const int w    = tid >> 5;
    const int lane = tid & 31;

    // ---- group 0: bias + A (x tile) + B (w2 group tile)
    if (tid < 49)
        cp_async4(sb + F_BIAS + tid * 4, b2 + g * 49 + tid);
    {
        const __half* asrc = g_xh + (size_t)(b * 32 + tile) * 8192;
        #pragma unroll
        for (int i = tid; i < 1024; i += 256)
            cp_async16(sb + F_A + i * 16, asrc + i * 8);
        const __half* bsrc = g_w2g + g * 4096;
        #pragma unroll
        for (int i = tid; i < 512; i += 256)
            cp_async16(sb + F_B + i * 16, bsrc + i * 8);
    }
    cp_commit();

    // ---- group 1: feature tile + halo (aligned 16B chunks, zfill OOB)
    {
        const float* fch0 = feat + (size_t)(b * 256 + g * 16) * HW;
        for (int i = tid; i < 1408; i += 256) {
            int c   = i / 88;
            int rem = i - c * 88;
            int yy  = rem >> 2;
            int q   = rem & 3;
            int gy  = y0 + yy - 3;
            int gx0 = x0 - 4 + q * 4;
            bool ok = ((unsigned)gy < 64u) && ((unsigned)gx0 <= 60u);
            const float* src = fch0 + (size_t)c * HW + (ok ? gy * WDIM + gx0 : 0);
            cp_async16z(sb + F_F + (c * FCH + yy * FRS + q * 4) * 4, src, ok ? 16 : 0);
        }
    }
    cp_commit();

    asm volatile("cp.async.wait_group 1;");   // A/B/bias ready; f in flight
    __syncthreads();

    // ---- MMA phase: wgt = w2_g @ x + b2 (in-register, bias-seeded)
    {
        const int kc = (lane & 3) * 2;
        float acc[8][4];
        #pragma unroll
        for (int nt = 0; nt < 8; nt++) {
            int k = nt * 8 + kc;
            float be = (k < 49) ? bias_s[k] : 0.f;
            float bo = (k + 1 < 49) ? bias_s[k + 1] : 0.f;
            acc[nt][0] = be; acc[nt][1] = bo;
            acc[nt][2] = be; acc[nt][3] = bo;
        }

        const int lrow = lane & 15;
        const int lcb  = lane >> 4;
        #pragma unroll
        for (int ks = 0; ks < 4; ks++) {
            uint32_t a[4];
            {
                uint32_t off = sw128((uint32_t)((w * 16 + lrow) * 128 + ks * 32 + lcb * 16));
                ldsm4(a, sb + F_A + off);
            }
            #pragma unroll
            for (int ntp = 0; ntp < 4; ntp++) {
                uint32_t bf[4];
                uint32_t off = sw128((uint32_t)((ntp * 16 + lrow) * 128 + ks * 32 + lcb * 16));
                ldsm4(bf, sb + F_B + off);
                mma16816(acc[2 * ntp],     a, bf[0], bf[2]);
                mma16816(acc[2 * ntp + 1], a, bf[1], bf[3]);
            }
        }

        // scatter fragments to wgt_sh[k][inner], row stride 132 (conflict-free)
        const int inner0 = w * 16 + (lane >> 2);
        #pragma unroll
        for (int nt = 0; nt < 7; nt++) {
            int k = nt * 8 + kc;
            float* row = wgt_sh + k * WGS;
            if (k < 49)     { row[inner0] = acc[nt][0];       row[inner0 + 8] = acc[nt][2]; }
            if (k + 1 < 49) { row[WGS + inner0] = acc[nt][1]; row[WGS + inner0 + 8] = acc[nt][3]; }
        }
    }

    asm volatile("cp.async.wait_group 0;");   // f complete (hidden under MMA)
    __syncthreads();

    // ---- aggregation phase (R12-proven, wgt stride 132)
    {
        const int rowA = 2 * w + (lane >> 4);
        const int c    = lane & 15;

        const float* fbase = f_sh + c * FCH;
        const float* wbase = wgt_sh + rowA * 8;

        ull accp[4] = {0ull, 0ull, 0ull, 0ull};

        #pragma unroll 1
        for (int di = 0; di < 7; di++) {
            const float* frow = fbase + (rowA + di) * FRS;
            float4 A = *(const float4*)(frow);
            float4 B = *(const float4*)(frow + 4);
            float4 C = *(const float4*)(frow + 8);
            float4 D = *(const float4*)(frow + 12);
            ull fra[7];
            fra[1] = pack2(A.z, A.w); fra[2] = pack2(B.x, B.y);
            fra[3] = pack2(B.z, B.w); fra[4] = pack2(C.x, C.y);
            fra[5] = pack2(C.z, C.w); fra[6] = pack2(D.x, D.y);
            ull frb[7];
            frb[0] = pack2(A.y, A.z); frb[1] = pack2(A.w, B.x);
            frb[2] = pack2(B.y, B.z); frb[3] = pack2(B.w, C.x);
            frb[4] = pack2(C.y, C.z); frb[5] = pack2(C.w, D.x);
            frb[6] = pack2(D.y, D.z);

            #pragma unroll
            for (int dj = 0; dj < 7; dj += 2) {
                int k = di * 7 + dj;
                ulonglong2 wv01 = *(const ulonglong2*)(wbase + k * WGS);
                ulonglong2 wv23 = *(const ulonglong2*)(wbase + k * WGS + 4);
                int s = dj >> 1;
                fma2(accp[0], wv01.x, frb[s]);
                fma2(accp[1], wv01.y, frb[s + 1]);
                fma2(accp[2], wv23.x, frb[s + 2]);
                fma2(accp[3], wv23.y, frb[s + 3]);
            }
            #pragma unroll
            for (int dj = 1; dj < 7; dj += 2) {
                int k = di * 7 + dj;
                ulonglong2 wv01 = *(const ulonglong2*)(wbase + k * WGS);
                ulonglong2 wv23 = *(const ulonglong2*)(wbase + k * WGS + 4);
                int s = (dj + 1) >> 1;
                fma2(accp[0], wv01.x, fra[s]);
                fma2(accp[1], wv01.y, fra[s + 1]);
                fma2(accp[2], wv23.x, fra[s + 2]);
                fma2(accp[3], wv23.y, fra[s + 3]);
            }
        }

        float acc[8];
        unpack2(accp[0], acc[0], acc[1]);
        unpack2(accp[1], acc[2], acc[3]);
        unpack2(accp[2], acc[4], acc[5]);
        unpack2(accp[3], acc[6], acc[7]);
        #pragma unroll
        for (int j = 0; j < 8; j++)
            acc[j] += fbase[(rowA + 3) * FRS + j + 4];

        float* op = &out[(size_t)(b * 256 + g * 16 + c) * HW + (y0 + rowA) * WDIM + x0];
        *(float4*)(op)     = make_float4(acc[0], acc[1], acc[2], acc[3]);
        *(float4*)(op + 4) = make_float4(acc[4], acc[5], acc[6], acc[7]);
    }
}

// ---------------------------------------------------------------------------
extern "C" void kernel_launch(void* const* d_in, const int* in_sizes, int n_in,
                              void* d_out, int out_size)
{
    const float* feat  = (const float*)d_in[0];
    const float* guide = (const float*)d_in[1];
    const float* w1    = (const float*)d_in[2];
    const float* gamma = (const float*)d_in[3];
    const float* beta  = (const float*)d_in[4];
    const float* mean  = (const float*)d_in[5];
    const float* var   = (const float*)d_in[6];
    const float* w2    = (const float*)d_in[7];
    const float* b2    = (const float*)d_in[8];
    float* out = (float*)d_out;

    prep_kernel<<<256, 256>>>(w1, gamma, beta, mean, var, w2);

    const int c1_smem = (16384 + 2 * C1G) * 4;            // 100352
    cudaFuncSetAttribute(conv1_kernel,
                         cudaFuncAttributeMaxDynamicSharedMemorySize, c1_smem);
    conv1_kernel<<<dim3(64, 4), 256, c1_smem>>>(guide);

    cudaFuncSetAttribute(fused2_kernel,
                         cudaFuncAttributeMaxDynamicSharedMemorySize, F_SIZE);
    fused2_kernel<<<dim3(16, 32, 4), 256, F_SIZE>>>(feat, b2, out);
}